// round 7
// baseline (speedup 1.0000x reference)
#include <cuda_runtime.h>
#include <cuda_bf16.h>
#include <cstdint>
#include <math.h>

#define N 8192
#define D 768
#define INV_T 20.0f
#define DIAG_SUB 2.0e13f      /* 1e12 * 20 */
#define EPSN 1e-8f

#define BM 128
#define BN 128
#define SPLIT 16
#define JT 4                   /* j-tiles per CTA */
#define BK 64                  /* K int8 per chunk (64 bytes) */
#define NKC (D / BK)           /* 12 chunks per j-tile */
#define NCH (JT * NKC)         /* 48 chunks per CTA */
#define NSTG 4                 /* B ring stages */
#define RED_BLOCKS (N / 256)   /* 32 */

#define AST 784                /* A smem row stride (768 + 16) */
#define BST 80                 /* B smem row stride (64 + 16) */
#define A_BYTES (BM * AST)     /* 100352 */
#define B_BYTES (BM * BST)     /* 10240 per stage */
#define SMEM_DYN (A_BYTES + NSTG * B_BYTES)   /* 141312 */

// ---------------------------------------------------------------------------
// device scratch (no cudaMalloc allowed)
// ---------------------------------------------------------------------------
__device__ signed char g_xq[N * D];    // quantized normalized rows
__device__ float g_scl[N];             // per-row quant scale
__device__ float g_mpart[SPLIT][N];
__device__ float g_spart[SPLIT][N];
__device__ float g_t[N];
__device__ float g_partial[RED_BLOCKS];

// ---------------------------------------------------------------------------
// PTX helpers (baseline PTX only)
// ---------------------------------------------------------------------------
__device__ __forceinline__ void cp_async16(uint32_t saddr, const void* gptr) {
    asm volatile("cp.async.cg.shared.global [%0], [%1], 16;"
                 :: "r"(saddr), "l"(__cvta_generic_to_global(gptr)) : "memory");
}
#define CP_COMMIT() asm volatile("cp.async.commit_group;" ::: "memory")
#define CP_WAIT(n)  asm volatile("cp.async.wait_group %0;" :: "n"(n) : "memory")

__device__ __forceinline__ void ldsm_x4(uint32_t* r, uint32_t addr) {
    asm volatile("ldmatrix.sync.aligned.m8n8.x4.shared.b16 {%0,%1,%2,%3}, [%4];"
                 : "=r"(r[0]), "=r"(r[1]), "=r"(r[2]), "=r"(r[3]) : "r"(addr));
}

__device__ __forceinline__ void mma_s8(int* d, const uint32_t* a,
                                       uint32_t b0, uint32_t b1) {
    asm volatile(
        "mma.sync.aligned.m16n8k32.row.col.s32.s8.s8.s32 "
        "{%0,%1,%2,%3}, {%4,%5,%6,%7}, {%8,%9}, {%0,%1,%2,%3};"
        : "+r"(d[0]), "+r"(d[1]), "+r"(d[2]), "+r"(d[3])
        : "r"(a[0]), "r"(a[1]), "r"(a[2]), "r"(a[3]), "r"(b0), "r"(b1));
}

// ---------------------------------------------------------------------------
// Kernel 1: row L2 norm + maxabs -> int8 quantize (per-row scale)
// ---------------------------------------------------------------------------
__global__ void normalize_kernel(const float* __restrict__ x) {
    int row = blockIdx.x;
    int tid = threadIdx.x;
    __shared__ float reds[8], redm[8];

    float ss = 0.0f, mx = 0.0f;
    #pragma unroll
    for (int c = tid; c < D; c += 256) {
        float v = x[row * D + c];
        ss = fmaf(v, v, ss);
        mx = fmaxf(mx, fabsf(v));
    }
    #pragma unroll
    for (int o = 16; o; o >>= 1) {
        ss += __shfl_down_sync(0xffffffffu, ss, o);
        mx = fmaxf(mx, __shfl_down_sync(0xffffffffu, mx, o));
    }
    if ((tid & 31) == 0) { reds[tid >> 5] = ss; redm[tid >> 5] = mx; }
    __syncthreads();
    if (tid < 8) {
        float s = reds[tid], m = redm[tid];
        #pragma unroll
        for (int o = 4; o; o >>= 1) {
            s += __shfl_down_sync(0xffu, s, o);
            m = fmaxf(m, __shfl_down_sync(0xffu, m, o));
        }
        if (tid == 0) { reds[0] = s; redm[0] = m; }
    }
    __syncthreads();
    float inv = 1.0f / fmaxf(sqrtf(reds[0]), EPSN);
    float sq  = fmaxf(redm[0] * inv * (1.0f / 127.0f), 1e-30f);  // xn maxabs / 127
    float qk  = inv / sq;                                         // x -> q multiplier
    #pragma unroll
    for (int c = tid; c < D; c += 256) {
        g_xq[row * D + c] = (signed char)__float2int_rn(x[row * D + c] * qk);
    }
    if (tid == 0) g_scl[row] = sq;
}

// ---------------------------------------------------------------------------
// Kernel 2: int8 mma.sync sim-GEMM + fused online LSE
// grid = (64, SPLIT), block = 512 (16 warps 4x4; warp tile 32x32)
// A tile (128x768 s8) SMEM-resident; B streamed BK=64 chunks, 4-stage ring.
// ---------------------------------------------------------------------------
__global__ void __launch_bounds__(512, 1) simloss_kernel() {
    extern __shared__ __align__(16) char smem[];

    const int tid   = threadIdx.x;
    const int lane  = tid & 31;
    const int w     = tid >> 5;
    const int wm    = w & 3;          // warp row  (32 rows)
    const int wn    = w >> 2;         // warp col  (32 cols)
    const int rt    = blockIdx.x;
    const int split = blockIdx.y;
    const int r0    = rt * BM;

    const uint32_t sA  = (uint32_t)__cvta_generic_to_shared(smem);
    const uint32_t sB0 = sA + A_BYTES;

    // ---- group 0: A tile (128 x 768B) ----
    {
        #pragma unroll
        for (int it = 0; it < 12; ++it) {
            int idx = tid + it * 512;           // 0..6143
            int row = idx / 48;
            int u   = idx % 48;
            cp_async16(sA + row * AST + u * 16,
                       (const char*)g_xq + (size_t)(r0 + row) * D + u * 16);
        }
        CP_COMMIT();
    }

    const int brow  = tid >> 2;        // 0..127
    const int bslot = tid & 3;         // 16B slot (64B row)

    // groups 1..3: chunks 0..2
    #pragma unroll
    for (int p = 0; p < NSTG - 1; ++p) {
        const int j0 = (split * JT + p / NKC) * BN;
        cp_async16(sB0 + (uint32_t)p * B_BYTES + brow * BST + bslot * 16,
                   (const char*)g_xq + (size_t)(j0 + brow) * D
                       + (p % NKC) * BK + bslot * 16);
        CP_COMMIT();
    }

    const uint32_t aAddrBase = sA + (wm * 32 + (lane & 15)) * AST + (lane >> 4) * 16;
    const uint32_t bRowOff   = (wn * 32 + (lane & 15)) * BST + (lane >> 4) * 16;

    const int i_base    = r0 + wm * 32 + (lane >> 2);
    const int jcol_base = wn * 32 + (lane & 3) * 2;

    // per-thread row scales folded with 1/T
    float prow[2][2];
    #pragma unroll
    for (int mt = 0; mt < 2; ++mt)
        #pragma unroll
        for (int rh = 0; rh < 2; ++rh)
            prow[mt][rh] = INV_T * g_scl[i_base + mt * 16 + rh * 8];

    float rm[2][2], rs[2][2];
    #pragma unroll
    for (int a = 0; a < 2; ++a)
        #pragma unroll
        for (int b = 0; b < 2; ++b) { rm[a][b] = -INFINITY; rs[a][b] = 0.0f; }

    for (int jt = 0; jt < JT; ++jt) {
        const int j0 = (split * JT + jt) * BN;
        int acc[2][4][4];
        #pragma unroll
        for (int mt = 0; mt < 2; ++mt)
            #pragma unroll
            for (int nt = 0; nt < 4; ++nt)
                #pragma unroll
                for (int c = 0; c < 4; ++c) acc[mt][nt][c] = 0;

        for (int kc = 0; kc < NKC; ++kc) {
            const int c = jt * NKC + kc;
            CP_WAIT(2);                 // chunk c arrived (c+1, c+2 may be pending)
            __syncthreads();            // all warps done reading buf (c+3)%NSTG

            // prefetch chunk c+3 into ring slot (c+3)%NSTG
            {
                const int p = c + NSTG - 1;
                if (p < NCH) {
                    const int pj0 = (split * JT + p / NKC) * BN;
                    cp_async16(sB0 + (uint32_t)(p % NSTG) * B_BYTES + brow * BST + bslot * 16,
                               (const char*)g_xq + (size_t)(pj0 + brow) * D
                                   + (p % NKC) * BK + bslot * 16);
                }
                CP_COMMIT();            // keep group counts aligned
            }

            // batched fragment loads, then all MMAs
            const uint32_t sB = sB0 + (uint32_t)(c % NSTG) * B_BYTES;
            uint32_t af[2][2][4], bf[2][2][4];
            #pragma unroll
            for (int ks = 0; ks < 2; ++ks)
                #pragma unroll
                for (int mt = 0; mt < 2; ++mt)
                    ldsm_x4(af[ks][mt], aAddrBase + mt * 16 * AST + kc * BK + ks * 32);
            #pragma unroll
            for (int ks = 0; ks < 2; ++ks)
                #pragma unroll
                for (int g = 0; g < 2; ++g)
                    ldsm_x4(bf[ks][g], sB + bRowOff + g * 16 * BST + ks * 32);

            #pragma unroll
            for (int ks = 0; ks < 2; ++ks)
                #pragma unroll
                for (int mt = 0; mt < 2; ++mt)
                    #pragma unroll
                    for (int nt = 0; nt < 4; ++nt) {
                        const int g = nt >> 1, hi = nt & 1;
                        mma_s8(acc[mt][nt], af[ks][mt], bf[ks][g][hi], bf[ks][g][hi + 2]);
                    }
        }

        // ---- epilogue: dequant+scale, mask, label, online LSE ----
        float scj[4][2];
        #pragma unroll
        for (int nt = 0; nt < 4; ++nt)
            #pragma unroll
            for (int cp = 0; cp < 2; ++cp)
                scj[nt][cp] = g_scl[j0 + jcol_base + nt * 8 + cp];

        #pragma unroll
        for (int mt = 0; mt < 2; ++mt)
            #pragma unroll
            for (int rh = 0; rh < 2; ++rh) {
                const int i = i_base + mt * 16 + rh * 8;
                const float pr = prow[mt][rh];
                float v[8];
                float mx = -INFINITY;
                #pragma unroll
                for (int nt = 0; nt < 4; ++nt)
                    #pragma unroll
                    for (int cp = 0; cp < 2; ++cp) {
                        const int j = j0 + jcol_base + nt * 8 + cp;
                        float f = (float)acc[mt][nt][rh * 2 + cp] * (pr * scj[nt][cp]);
                        if (j == i) f -= DIAG_SUB;
                        if (j == (i ^ 1)) g_t[i] = f;
                        v[nt * 2 + cp] = f;
                        mx = fmaxf(mx, f);
                    }
                const float nm = fmaxf(rm[mt][rh], mx);
                float s = 0.0f;
                #pragma unroll
                for (int q = 0; q < 8; ++q) s += __expf(v[q] - nm);
                rs[mt][rh] = rs[mt][rh] * __expf(rm[mt][rh] - nm) + s;
                rm[mt][rh] = nm;
            }
    }

    // ---- merge (m,s): lanes sharing a row, then the 4 warp-columns ----
    CP_WAIT(0);
    __syncthreads();                       // smem reusable
    float* bufm = (float*)smem;            // [4][BM]
    float* bufs = bufm + 4 * BM;           // [4][BM]

    #pragma unroll
    for (int mt = 0; mt < 2; ++mt)
        #pragma unroll
        for (int rh = 0; rh < 2; ++rh) {
            float m = rm[mt][rh], s = rs[mt][rh];
            #pragma unroll
            for (int off = 1; off <= 2; off <<= 1) {
                float mo = __shfl_xor_sync(0xffffffffu, m, off);
                float so = __shfl_xor_sync(0xffffffffu, s, off);
                float mn = fmaxf(m, mo);
                s = s * __expf(m - mn) + so * __expf(mo - mn);
                m = mn;
            }
            if ((lane & 3) == 0) {
                const int rl = wm * 32 + (lane >> 2) + mt * 16 + rh * 8;
                bufm[wn * BM + rl] = m;
                bufs[wn * BM + rl] = s;
            }
        }
    __syncthreads();

    if (tid < BM) {
        float M = -INFINITY;
        #pragma unroll
        for (int q = 0; q < 4; ++q) M = fmaxf(M, bufm[q * BM + tid]);
        float S = 0.0f;
        #pragma unroll
        for (int q = 0; q < 4; ++q) S += bufs[q * BM + tid] * __expf(bufm[q * BM + tid] - M);
        g_mpart[split][r0 + tid] = M;
        g_spart[split][r0 + tid] = S;
    }
}

// ---------------------------------------------------------------------------
// Kernel 3: merge splits per row, per-block deterministic partial sums
// ---------------------------------------------------------------------------
__global__ void reduce_rows_kernel() {
    const int row = blockIdx.x * 256 + threadIdx.x;
    __shared__ float red[8];

    float M = -INFINITY;
    #pragma unroll
    for (int s = 0; s < SPLIT; ++s) M = fmaxf(M, g_mpart[s][row]);
    float S = 0.0f;
    #pragma unroll
    for (int s = 0; s < SPLIT; ++s) S += g_spart[s][row] * __expf(g_mpart[s][row] - M);
    float li = (M + logf(S)) - g_t[row];

    #pragma unroll
    for (int o = 16; o; o >>= 1) li += __shfl_down_sync(0xffffffffu, li, o);
    if ((threadIdx.x & 31) == 0) red[threadIdx.x >> 5] = li;
    __syncthreads();
    if (threadIdx.x < 8) {
        float v = red[threadIdx.x];
        #pragma unroll
        for (int o = 4; o; o >>= 1) v += __shfl_down_sync(0xffu, v, o);
        if (threadIdx.x == 0) g_partial[blockIdx.x] = v;
    }
}

// ---------------------------------------------------------------------------
// Kernel 4: final deterministic sum -> mean
// ---------------------------------------------------------------------------
__global__ void final_kernel(float* __restrict__ out) {
    float v = g_partial[threadIdx.x];
    #pragma unroll
    for (int o = 16; o; o >>= 1) v += __shfl_down_sync(0xffffffffu, v, o);
    if (threadIdx.x == 0) out[0] = v * (1.0f / (float)N);
}

extern "C" void kernel_launch(void* const* d_in, const int* in_sizes, int n_in,
                              void* d_out, int out_size) {
    const float* x = (const float*)d_in[0];
    float* out = (float*)d_out;

    cudaFuncSetAttribute(simloss_kernel,
                         cudaFuncAttributeMaxDynamicSharedMemorySize, SMEM_DYN);

    normalize_kernel<<<N, 256>>>(x);
    dim3 grid(N / BM, SPLIT);
    simloss_kernel<<<grid, 512, SMEM_DYN>>>();
    reduce_rows_kernel<<<RED_BLOCKS, 256>>>();
    final_kernel<<<1, 32>>>(out);
}

// round 8
// speedup vs baseline: 3.6054x; 3.6054x over previous
#include <cuda_runtime.h>
#include <cuda_bf16.h>
#include <cstdint>
#include <math.h>

#define N 8192
#define D 768
#define INV_T 20.0f
#define DIAG_SUB 2.0e13f      /* 1e12 * 20 */
#define EPSN 1e-8f

#define NT 64                  /* 8192/128 tile blocks per dim */
#define NTILES 2080            /* NT*(NT+1)/2 upper-tri tiles */
#define BK 32                  /* K bf16 per chunk */
#define NCH (D / BK)           /* 24 chunks per tile */
#define NSTG 4                 /* ring stages */
#define RED_BLOCKS (N / 256)   /* 32 */

#define BST 80                 /* smem row stride (64B data + 16 pad) */
#define TILE_BYTES (128 * BST) /* 10240 per operand per stage */
#define STG_BYTES (2 * TILE_BYTES)
#define SMEM_DYN (NSTG * STG_BYTES)   /* 81920 */

// ---------------------------------------------------------------------------
// device scratch (no cudaMalloc allowed)
// ---------------------------------------------------------------------------
__device__ __nv_bfloat16 g_xnb[N * D];
__device__ float g_m2[NT][N];
__device__ float g_s2[NT][N];
__device__ float g_t[N];
__device__ float g_partial[RED_BLOCKS];

// ---------------------------------------------------------------------------
// PTX helpers (baseline PTX only)
// ---------------------------------------------------------------------------
__device__ __forceinline__ void cp_async16(uint32_t saddr, const void* gptr) {
    asm volatile("cp.async.cg.shared.global [%0], [%1], 16;"
                 :: "r"(saddr), "l"(__cvta_generic_to_global(gptr)) : "memory");
}
#define CP_COMMIT() asm volatile("cp.async.commit_group;" ::: "memory")
#define CP_WAIT(n)  asm volatile("cp.async.wait_group %0;" :: "n"(n) : "memory")

__device__ __forceinline__ void ldsm_x4(uint32_t* r, uint32_t addr) {
    asm volatile("ldmatrix.sync.aligned.m8n8.x4.shared.b16 {%0,%1,%2,%3}, [%4];"
                 : "=r"(r[0]), "=r"(r[1]), "=r"(r[2]), "=r"(r[3]) : "r"(addr));
}

__device__ __forceinline__ void mma_bf16(float* d, const uint32_t* a,
                                         uint32_t b0, uint32_t b1) {
    asm volatile(
        "mma.sync.aligned.m16n8k16.row.col.f32.bf16.bf16.f32 "
        "{%0,%1,%2,%3}, {%4,%5,%6,%7}, {%8,%9}, {%0,%1,%2,%3};"
        : "+f"(d[0]), "+f"(d[1]), "+f"(d[2]), "+f"(d[3])
        : "r"(a[0]), "r"(a[1]), "r"(a[2]), "r"(a[3]), "r"(b0), "r"(b1));
}

// ---------------------------------------------------------------------------
// Kernel 1: row L2 norms + normalize -> bf16
// ---------------------------------------------------------------------------
__global__ void normalize_kernel(const float* __restrict__ x) {
    int row = blockIdx.x;
    int tid = threadIdx.x;
    __shared__ float red[8];

    float ss = 0.0f;
    #pragma unroll
    for (int c = tid; c < D; c += 256) {
        float v = x[row * D + c];
        ss = fmaf(v, v, ss);
    }
    #pragma unroll
    for (int o = 16; o; o >>= 1) ss += __shfl_down_sync(0xffffffffu, ss, o);
    if ((tid & 31) == 0) red[tid >> 5] = ss;
    __syncthreads();
    if (tid < 8) {
        float v = red[tid];
        #pragma unroll
        for (int o = 4; o; o >>= 1) v += __shfl_down_sync(0xffu, v, o);
        if (tid == 0) red[0] = v;
    }
    __syncthreads();
    float inv = 1.0f / fmaxf(sqrtf(red[0]), EPSN);
    #pragma unroll
    for (int c = tid; c < D; c += 256) {
        g_xnb[row * D + c] = __float2bfloat16(x[row * D + c] * inv);
    }
}

// ---------------------------------------------------------------------------
// Kernel 2: upper-triangular bf16 sim-GEMM; each tile feeds BOTH the row
// block (direct LSE) and the column block (transposed LSE).
// grid = NTILES, block = 512 (16 warps 4x4; warp tile 32x32).
// ---------------------------------------------------------------------------
__global__ void __launch_bounds__(512, 1) simloss_kernel() {
    extern __shared__ __align__(16) char smem[];

    const int tid  = threadIdx.x;
    const int lane = tid & 31;
    const int w    = tid >> 5;
    const int wm   = w & 3;
    const int wn   = w >> 2;

    // decode upper-triangular tile index
    const int t = blockIdx.x;
    int ti = (int)(64.5f - sqrtf(64.5f * 64.5f - 2.0f * (float)t));
    while (ti * NT - ti * (ti - 1) / 2 > t) --ti;
    while ((ti + 1) * NT - (ti + 1) * ti / 2 <= t) ++ti;
    const int tj   = ti + (t - (ti * NT - ti * (ti - 1) / 2));
    const bool diag = (ti == tj);
    const int r0 = ti * 128;
    const int j0 = tj * 128;

    const uint32_t sBase = (uint32_t)__cvta_generic_to_shared(smem);

    const int brow  = tid >> 2;        // 0..127
    const int bslot = tid & 3;         // 16B slot of 64B row

    // prologue: chunks 0..2 (A + B per stage, one commit group each)
    #pragma unroll
    for (int p = 0; p < NSTG - 1; ++p) {
        const uint32_t sStg = sBase + (uint32_t)p * STG_BYTES;
        cp_async16(sStg + brow * BST + bslot * 16,
                   (const char*)g_xnb + (size_t)(r0 + brow) * (D * 2) + p * 64 + bslot * 16);
        cp_async16(sStg + TILE_BYTES + brow * BST + bslot * 16,
                   (const char*)g_xnb + (size_t)(j0 + brow) * (D * 2) + p * 64 + bslot * 16);
        CP_COMMIT();
    }

    const uint32_t aRowOff = (wm * 32 + (lane & 15)) * BST + (lane >> 4) * 16;
    const uint32_t bRowOff = (wn * 32 + (lane & 15)) * BST + (lane >> 4) * 16;

    const int i_base    = r0 + wm * 32 + (lane >> 2);
    const int jcol_base = wn * 32 + (lane & 3) * 2;

    float acc[2][4][4];
    #pragma unroll
    for (int mt = 0; mt < 2; ++mt)
        #pragma unroll
        for (int nt = 0; nt < 4; ++nt)
            #pragma unroll
            for (int c = 0; c < 4; ++c) acc[mt][nt][c] = 0.0f;

    for (int c = 0; c < NCH; ++c) {
        CP_WAIT(2);
        __syncthreads();

        // prefetch chunk c+3
        {
            const int p = c + NSTG - 1;
            if (p < NCH) {
                const uint32_t sStg = sBase + (uint32_t)(p % NSTG) * STG_BYTES;
                cp_async16(sStg + brow * BST + bslot * 16,
                           (const char*)g_xnb + (size_t)(r0 + brow) * (D * 2) + p * 64 + bslot * 16);
                cp_async16(sStg + TILE_BYTES + brow * BST + bslot * 16,
                           (const char*)g_xnb + (size_t)(j0 + brow) * (D * 2) + p * 64 + bslot * 16);
            }
            CP_COMMIT();
        }

        const uint32_t sStg = sBase + (uint32_t)(c % NSTG) * STG_BYTES;
        uint32_t af[2][2][4], bf[2][2][4];
        #pragma unroll
        for (int ks = 0; ks < 2; ++ks)
            #pragma unroll
            for (int mt = 0; mt < 2; ++mt)
                ldsm_x4(af[ks][mt], sStg + aRowOff + mt * 16 * BST + ks * 32);
        #pragma unroll
        for (int ks = 0; ks < 2; ++ks)
            #pragma unroll
            for (int g = 0; g < 2; ++g)
                ldsm_x4(bf[ks][g], sStg + TILE_BYTES + bRowOff + g * 16 * BST + ks * 32);

        #pragma unroll
        for (int ks = 0; ks < 2; ++ks)
            #pragma unroll
            for (int mt = 0; mt < 2; ++mt)
                #pragma unroll
                for (int nt = 0; nt < 4; ++nt) {
                    const int g = nt >> 1, hi = nt & 1;
                    mma_bf16(acc[mt][nt], af[ks][mt], bf[ks][g][hi], bf[ks][g][hi + 2]);
                }
    }

    // ---- epilogues: smem ring dead, reuse as merge buffers ----
    CP_WAIT(0);
    __syncthreads();
    float* bufm  = (float*)smem;           // [4][128] direct
    float* bufs  = bufm + 4 * 128;
    float* bufm2 = bufs + 4 * 128;         // [4][128] transposed
    float* bufs2 = bufm2 + 4 * 128;

    // direct: per-row (m,s) over this tile's 128 columns
    #pragma unroll
    for (int mt = 0; mt < 2; ++mt)
        #pragma unroll
        for (int rh = 0; rh < 2; ++rh) {
            const int i = i_base + mt * 16 + rh * 8;
            float v[8];
            float mx = -INFINITY;
            #pragma unroll
            for (int nt = 0; nt < 4; ++nt)
                #pragma unroll
                for (int cp = 0; cp < 2; ++cp) {
                    const int j = j0 + jcol_base + nt * 8 + cp;
                    float f = acc[mt][nt][rh * 2 + cp] * INV_T;
                    if (diag) {
                        if (j == i) f -= DIAG_SUB;
                        if (j == (i ^ 1)) g_t[i] = f;
                    }
                    v[nt * 2 + cp] = f;
                    mx = fmaxf(mx, f);
                }
            float s = 0.0f;
            #pragma unroll
            for (int q = 0; q < 8; ++q) s += __expf(v[q] - mx);
            // merge across the 4 lanes sharing this row
            #pragma unroll
            for (int off = 1; off <= 2; off <<= 1) {
                float mo = __shfl_xor_sync(0xffffffffu, mx, off);
                float so = __shfl_xor_sync(0xffffffffu, s,  off);
                float mn = fmaxf(mx, mo);
                s = s * __expf(mx - mn) + so * __expf(mo - mn);
                mx = mn;
            }
            if ((lane & 3) == 0) {
                const int rl = wm * 32 + (lane >> 2) + mt * 16 + rh * 8;
                bufm[wn * 128 + rl] = mx;
                bufs[wn * 128 + rl] = s;
            }
        }

    // transposed (off-diagonal only): per-column (m,s) over 128 rows
    if (!diag) {
        #pragma unroll
        for (int nt = 0; nt < 4; ++nt)
            #pragma unroll
            for (int cp = 0; cp < 2; ++cp) {
                float f0 = acc[0][nt][cp]     * INV_T;
                float f1 = acc[0][nt][2 + cp] * INV_T;
                float f2 = acc[1][nt][cp]     * INV_T;
                float f3 = acc[1][nt][2 + cp] * INV_T;
                float mx = fmaxf(fmaxf(f0, f1), fmaxf(f2, f3));
                float s  = __expf(f0 - mx) + __expf(f1 - mx)
                         + __expf(f2 - mx) + __expf(f3 - mx);
                // merge across the 8 lanes sharing this column
                #pragma unroll
                for (int off = 4; off <= 16; off <<= 1) {
                    float mo = __shfl_xor_sync(0xffffffffu, mx, off);
                    float so = __shfl_xor_sync(0xffffffffu, s,  off);
                    float mn = fmaxf(mx, mo);
                    s = s * __expf(mx - mn) + so * __expf(mo - mn);
                    mx = mn;
                }
                if (lane < 4) {
                    const int col = wn * 32 + nt * 8 + (lane & 3) * 2 + cp;
                    bufm2[wm * 128 + col] = mx;
                    bufs2[wm * 128 + col] = s;
                }
            }
    }
    __syncthreads();

    if (tid < 128) {
        // direct partial -> slot tj, rows of block ti
        float M = -INFINITY;
        #pragma unroll
        for (int q = 0; q < 4; ++q) M = fmaxf(M, bufm[q * 128 + tid]);
        float S = 0.0f;
        #pragma unroll
        for (int q = 0; q < 4; ++q) S += bufs[q * 128 + tid] * __expf(bufm[q * 128 + tid] - M);
        g_m2[tj][r0 + tid] = M;
        g_s2[tj][r0 + tid] = S;

        if (!diag) {
            // transposed partial -> slot ti, rows of block tj
            float M2 = -INFINITY;
            #pragma unroll
            for (int q = 0; q < 4; ++q) M2 = fmaxf(M2, bufm2[q * 128 + tid]);
            float S2 = 0.0f;
            #pragma unroll
            for (int q = 0; q < 4; ++q) S2 += bufs2[q * 128 + tid] * __expf(bufm2[q * 128 + tid] - M2);
            g_m2[ti][j0 + tid] = M2;
            g_s2[ti][j0 + tid] = S2;
        }
    }
}

// ---------------------------------------------------------------------------
// Kernel 3: merge 64 slots per row, per-block deterministic partial sums
// ---------------------------------------------------------------------------
__global__ void reduce_rows_kernel() {
    const int row = blockIdx.x * 256 + threadIdx.x;
    __shared__ float red[8];

    float M = -INFINITY;
    for (int s = 0; s < NT; ++s) M = fmaxf(M, g_m2[s][row]);
    float S = 0.0f;
    for (int s = 0; s < NT; ++s) S += g_s2[s][row] * __expf(g_m2[s][row] - M);
    float li = (M + logf(S)) - g_t[row];

    #pragma unroll
    for (int o = 16; o; o >>= 1) li += __shfl_down_sync(0xffffffffu, li, o);
    if ((threadIdx.x & 31) == 0) red[threadIdx.x >> 5] = li;
    __syncthreads();
    if (threadIdx.x < 8) {
        float v = red[threadIdx.x];
        #pragma unroll
        for (int o = 4; o; o >>= 1) v += __shfl_down_sync(0xffu, v, o);
        if (threadIdx.x == 0) g_partial[blockIdx.x] = v;
    }
}

// ---------------------------------------------------------------------------
// Kernel 4: final deterministic sum -> mean
// ---------------------------------------------------------------------------
__global__ void final_kernel(float* __restrict__ out) {
    float v = g_partial[threadIdx.x];
    #pragma unroll
    for (int o = 16; o; o >>= 1) v += __shfl_down_sync(0xffffffffu, v, o);
    if (threadIdx.x == 0) out[0] = v * (1.0f / (float)N);
}

extern "C" void kernel_launch(void* const* d_in, const int* in_sizes, int n_in,
                              void* d_out, int out_size) {
    const float* x = (const float*)d_in[0];
    float* out = (float*)d_out;

    cudaFuncSetAttribute(simloss_kernel,
                         cudaFuncAttributeMaxDynamicSharedMemorySize, SMEM_DYN);

    normalize_kernel<<<N, 256>>>(x);
    simloss_kernel<<<NTILES, 512, SMEM_DYN>>>();
    reduce_rows_kernel<<<RED_BLOCKS, 256>>>();
    final_kernel<<<1, 32>>>(out);
}

// round 9
// speedup vs baseline: 4.0678x; 1.1282x over previous
#include <cuda_runtime.h>
#include <cuda_bf16.h>
#include <cstdint>
#include <math.h>

#define N 8192
#define D 768
#define INV_T 20.0f
#define DIAG_SUB 2.0e13f      /* 1e12 * 20 */
#define EPSN 1e-8f

#define NT 64                  /* 8192/128 tile blocks per dim */
#define NTILES 2080            /* NT*(NT+1)/2 upper-tri tiles */
#define BK 32                  /* K bf16 per chunk */
#define NCH (D / BK)           /* 24 chunks per tile (divisible by NSTG) */
#define NSTG 4                 /* ring stages */
#define RED_BLOCKS (N / 256)   /* 32 */

#define BST 80                 /* smem row stride (64B data + 16 pad) */
#define TILE_BYTES (128 * BST) /* 10240 per operand per stage */
#define STG_BYTES (2 * TILE_BYTES)
#define RING_BYTES (NSTG * STG_BYTES)          /* 81920 */
#define SMEM_DYN (RING_BYTES + 2 * 4 * 128 * 4)  /* + direct/transposed sum bufs */

// ---------------------------------------------------------------------------
// device scratch (no cudaMalloc allowed)
// ---------------------------------------------------------------------------
__device__ __nv_bfloat16 g_xnb[N * D];
__device__ float g_s2[NT][N];          // per-(tile-slot, row) partial sums of exp(l-20)
__device__ float g_t[N];               // logits[i, i^1]
__device__ float g_partial[RED_BLOCKS];

// ---------------------------------------------------------------------------
// PTX helpers (baseline PTX only)
// ---------------------------------------------------------------------------
__device__ __forceinline__ void cp_async16(uint32_t saddr, const void* gptr) {
    asm volatile("cp.async.cg.shared.global [%0], [%1], 16;"
                 :: "r"(saddr), "l"(__cvta_generic_to_global(gptr)) : "memory");
}
#define CP_COMMIT() asm volatile("cp.async.commit_group;" ::: "memory")
#define CP_WAIT(n)  asm volatile("cp.async.wait_group %0;" :: "n"(n) : "memory")

__device__ __forceinline__ void ldsm_x4(uint32_t* r, uint32_t addr) {
    asm volatile("ldmatrix.sync.aligned.m8n8.x4.shared.b16 {%0,%1,%2,%3}, [%4];"
                 : "=r"(r[0]), "=r"(r[1]), "=r"(r[2]), "=r"(r[3]) : "r"(addr));
}

__device__ __forceinline__ void mma_bf16(float* d, const uint32_t* a,
                                         uint32_t b0, uint32_t b1) {
    asm volatile(
        "mma.sync.aligned.m16n8k16.row.col.f32.bf16.bf16.f32 "
        "{%0,%1,%2,%3}, {%4,%5,%6,%7}, {%8,%9}, {%0,%1,%2,%3};"
        : "+f"(d[0]), "+f"(d[1]), "+f"(d[2]), "+f"(d[3])
        : "r"(a[0]), "r"(a[1]), "r"(a[2]), "r"(a[3]), "r"(b0), "r"(b1));
}

__device__ __forceinline__ void decode_tile(int t, int& ti, int& tj) {
    int i = (int)(64.5f - sqrtf(64.5f * 64.5f - 2.0f * (float)t));
    while (i * NT - i * (i - 1) / 2 > t) --i;
    while ((i + 1) * NT - (i + 1) * i / 2 <= t) ++i;
    ti = i;
    tj = i + (t - (i * NT - i * (i - 1) / 2));
}

// ---------------------------------------------------------------------------
// Kernel 1: row L2 norms + normalize -> bf16
// ---------------------------------------------------------------------------
__global__ void normalize_kernel(const float* __restrict__ x) {
    int row = blockIdx.x;
    int tid = threadIdx.x;
    __shared__ float red[8];

    float ss = 0.0f;
    #pragma unroll
    for (int c = tid; c < D; c += 256) {
        float v = x[row * D + c];
        ss = fmaf(v, v, ss);
    }
    #pragma unroll
    for (int o = 16; o; o >>= 1) ss += __shfl_down_sync(0xffffffffu, ss, o);
    if ((tid & 31) == 0) red[tid >> 5] = ss;
    __syncthreads();
    if (tid < 8) {
        float v = red[tid];
        #pragma unroll
        for (int o = 4; o; o >>= 1) v += __shfl_down_sync(0xffu, v, o);
        if (tid == 0) red[0] = v;
    }
    __syncthreads();
    float inv = 1.0f / fmaxf(sqrtf(red[0]), EPSN);
    #pragma unroll
    for (int c = tid; c < D; c += 256) {
        g_xnb[row * D + c] = __float2bfloat16(x[row * D + c] * inv);
    }
}

// ---------------------------------------------------------------------------
// Kernel 2: persistent upper-triangular bf16 sim-GEMM, fixed-max softmax.
// grid = #SMs, block = 512. Ring rolls across tile boundaries.
// ---------------------------------------------------------------------------
__global__ void __launch_bounds__(512, 1) simloss_kernel() {
    extern __shared__ __align__(16) char smem[];

    const int tid  = threadIdx.x;
    const int lane = tid & 31;
    const int w    = tid >> 5;
    const int wm   = w & 3;
    const int wn   = w >> 2;
    const int G    = gridDim.x;

    const uint32_t sBase = (uint32_t)__cvta_generic_to_shared(smem);
    float* bufs  = (float*)(smem + RING_BYTES);          // [4][128] direct
    float* bufs2 = bufs + 4 * 128;                       // [4][128] transposed

    const int brow  = tid >> 2;
    const int bslot = tid & 3;

    int t_cur = blockIdx.x;
    if (t_cur >= NTILES) return;
    int ti, tj;
    decode_tile(t_cur, ti, tj);
    int r0 = ti * 128, j0 = tj * 128;

    int t_nxt = t_cur + G;
    bool has_nxt = (t_nxt < NTILES);
    int nti, ntj, nr0 = 0, nj0 = 0;
    if (has_nxt) { decode_tile(t_nxt, nti, ntj); nr0 = nti * 128; nj0 = ntj * 128; }

    // prologue: stages 0..2 = chunks 0..2 of first tile
    #pragma unroll
    for (int p = 0; p < NSTG - 1; ++p) {
        const uint32_t sStg = sBase + (uint32_t)p * STG_BYTES;
        cp_async16(sStg + brow * BST + bslot * 16,
                   (const char*)g_xnb + (size_t)(r0 + brow) * (D * 2) + p * 64 + bslot * 16);
        cp_async16(sStg + TILE_BYTES + brow * BST + bslot * 16,
                   (const char*)g_xnb + (size_t)(j0 + brow) * (D * 2) + p * 64 + bslot * 16);
        CP_COMMIT();
    }

    const uint32_t aRowOff = (wm * 32 + (lane & 15)) * BST + (lane >> 4) * 16;
    const uint32_t bRowOff = (wn * 32 + (lane & 15)) * BST + (lane >> 4) * 16;
    const int il_base   = wm * 32 + (lane >> 2);          // local row base
    const int jcol_base = wn * 32 + (lane & 3) * 2;       // local col base

    for (;;) {
        const bool diag = (r0 == j0);
        float acc[2][4][4];
        #pragma unroll
        for (int mt = 0; mt < 2; ++mt)
            #pragma unroll
            for (int nt = 0; nt < 4; ++nt)
                #pragma unroll
                for (int c = 0; c < 4; ++c) acc[mt][nt][c] = 0.0f;

        for (int kc = 0; kc < NCH; ++kc) {
            CP_WAIT(2);
            __syncthreads();

            // prefetch chunk kc+3 (rolls into next tile)
            {
                int p = kc + NSTG - 1;
                int pr0 = r0, pj0 = j0;
                bool go = true;
                if (p >= NCH) { p -= NCH; pr0 = nr0; pj0 = nj0; go = has_nxt; }
                if (go) {
                    const uint32_t sStg = sBase + (uint32_t)(p & 3) * STG_BYTES;
                    cp_async16(sStg + brow * BST + bslot * 16,
                               (const char*)g_xnb + (size_t)(pr0 + brow) * (D * 2) + p * 64 + bslot * 16);
                    cp_async16(sStg + TILE_BYTES + brow * BST + bslot * 16,
                               (const char*)g_xnb + (size_t)(pj0 + brow) * (D * 2) + p * 64 + bslot * 16);
                }
                CP_COMMIT();
            }

            const uint32_t sStg = sBase + (uint32_t)(kc & 3) * STG_BYTES;
            uint32_t af[2][2][4], bf[2][2][4];
            #pragma unroll
            for (int ks = 0; ks < 2; ++ks)
                #pragma unroll
                for (int mt = 0; mt < 2; ++mt)
                    ldsm_x4(af[ks][mt], sStg + aRowOff + mt * 16 * BST + ks * 32);
            #pragma unroll
            for (int ks = 0; ks < 2; ++ks)
                #pragma unroll
                for (int g = 0; g < 2; ++g)
                    ldsm_x4(bf[ks][g], sStg + TILE_BYTES + bRowOff + g * 16 * BST + ks * 32);

            #pragma unroll
            for (int ks = 0; ks < 2; ++ks)
                #pragma unroll
                for (int mt = 0; mt < 2; ++mt)
                    #pragma unroll
                    for (int nt = 0; nt < 4; ++nt) {
                        const int g = nt >> 1, hi = nt & 1;
                        mma_bf16(acc[mt][nt], af[ks][mt], bf[ks][g][hi], bf[ks][g][hi + 2]);
                    }
        }

        // ---- epilogue: exp(l - 20) in place, then plain-sum reductions ----
        if (!diag) {
            #pragma unroll
            for (int mt = 0; mt < 2; ++mt)
                #pragma unroll
                for (int nt = 0; nt < 4; ++nt)
                    #pragma unroll
                    for (int c = 0; c < 4; ++c)
                        acc[mt][nt][c] = __expf(fmaf(acc[mt][nt][c], INV_T, -INV_T));
        } else {
            #pragma unroll
            for (int mt = 0; mt < 2; ++mt)
                #pragma unroll
                for (int nt = 0; nt < 4; ++nt)
                    #pragma unroll
                    for (int c = 0; c < 4; ++c) {
                        const int i = r0 + il_base + mt * 16 + (c >> 1) * 8;
                        const int j = j0 + jcol_base + nt * 8 + (c & 1);
                        float l = acc[mt][nt][c] * INV_T;
                        if (j == i) l -= DIAG_SUB;
                        if (j == (i ^ 1)) g_t[i] = l;
                        acc[mt][nt][c] = __expf(l - INV_T);
                    }
        }

        // direct: per-row sums over 8 cols, merge lanes xor {1,2}
        #pragma unroll
        for (int mt = 0; mt < 2; ++mt)
            #pragma unroll
            for (int rh = 0; rh < 2; ++rh) {
                float s = 0.0f;
                #pragma unroll
                for (int nt = 0; nt < 4; ++nt)
                    #pragma unroll
                    for (int cp = 0; cp < 2; ++cp) s += acc[mt][nt][rh * 2 + cp];
                s += __shfl_xor_sync(0xffffffffu, s, 1);
                s += __shfl_xor_sync(0xffffffffu, s, 2);
                if ((lane & 3) == 0)
                    bufs[wn * 128 + il_base + mt * 16 + rh * 8] = s;
            }

        // transposed: per-col sums over 4 rows, merge lanes xor {4,8,16}
        if (!diag) {
            #pragma unroll
            for (int nt = 0; nt < 4; ++nt)
                #pragma unroll
                for (int cp = 0; cp < 2; ++cp) {
                    float s = acc[0][nt][cp] + acc[0][nt][2 + cp]
                            + acc[1][nt][cp] + acc[1][nt][2 + cp];
                    s += __shfl_xor_sync(0xffffffffu, s, 4);
                    s += __shfl_xor_sync(0xffffffffu, s, 8);
                    s += __shfl_xor_sync(0xffffffffu, s, 16);
                    if (lane < 4)
                        bufs2[wm * 128 + wn * 32 + nt * 8 + (lane & 3) * 2 + cp] = s;
                }
        }
        __syncthreads();

        if (tid < 128) {
            float S = bufs[tid] + bufs[128 + tid] + bufs[256 + tid] + bufs[384 + tid];
            g_s2[j0 >> 7][r0 + tid] = S;
            if (!diag) {
                float S2 = bufs2[tid] + bufs2[128 + tid] + bufs2[256 + tid] + bufs2[384 + tid];
                g_s2[r0 >> 7][j0 + tid] = S2;
            }
        }

        if (!has_nxt) break;
        r0 = nr0; j0 = nj0;
        t_nxt += G;
        has_nxt = (t_nxt < NTILES);
        if (has_nxt) { decode_tile(t_nxt, nti, ntj); nr0 = nti * 128; nj0 = ntj * 128; }
    }
}

// ---------------------------------------------------------------------------
// Kernel 3: sum 64 slots per row -> per-row loss; block partial sums
// ---------------------------------------------------------------------------
__global__ void reduce_rows_kernel() {
    const int row = blockIdx.x * 256 + threadIdx.x;
    __shared__ float red[8];

    float S = 0.0f;
    #pragma unroll 8
    for (int s = 0; s < NT; ++s) S += g_s2[s][row];
    float li = (INV_T + logf(S)) - g_t[row];

    #pragma unroll
    for (int o = 16; o; o >>= 1) li += __shfl_down_sync(0xffffffffu, li, o);
    if ((threadIdx.x & 31) == 0) red[threadIdx.x >> 5] = li;
    __syncthreads();
    if (threadIdx.x < 8) {
        float v = red[threadIdx.x];
        #pragma unroll
        for (int o = 4; o; o >>= 1) v += __shfl_down_sync(0xffu, v, o);
        if (threadIdx.x == 0) g_partial[blockIdx.x] = v;
    }
}

// ---------------------------------------------------------------------------
// Kernel 4: final deterministic sum -> mean
// ---------------------------------------------------------------------------
__global__ void final_kernel(float* __restrict__ out) {
    float v = g_partial[threadIdx.x];
    #pragma unroll
    for (int o = 16; o; o >>= 1) v += __shfl_down_sync(0xffffffffu, v, o);
    if (threadIdx.x == 0) out[0] = v * (1.0f / (float)N);
}

extern "C" void kernel_launch(void* const* d_in, const int* in_sizes, int n_in,
                              void* d_out, int out_size) {
    const float* x = (const float*)d_in[0];
    float* out = (float*)d_out;

    int nsm = 148;
    cudaDeviceGetAttribute(&nsm, cudaDevAttrMultiProcessorCount, 0);
    int grid = nsm < NTILES ? nsm : NTILES;

    cudaFuncSetAttribute(simloss_kernel,
                         cudaFuncAttributeMaxDynamicSharedMemorySize, SMEM_DYN);

    normalize_kernel<<<N, 256>>>(x);
    simloss_kernel<<<grid, 512, SMEM_DYN>>>();
    reduce_rows_kernel<<<RED_BLOCKS, 256>>>();
    final_kernel<<<1, 32>>>(out);
}